// round 1
// baseline (speedup 1.0000x reference)
#include <cuda_runtime.h>
#include <cuda_bf16.h>
#include <math.h>

// Problem constants
#define NQ   100
#define NT   197
#define BSZ  128
#define E    768
#define NH   12
#define HD   64
#define BH   (BSZ*NH)          // 1536

// ---------------------------------------------------------------------------
// Device scratch (no cudaMalloc allowed)
// ---------------------------------------------------------------------------
__device__ float g_qt[BH * HD * NQ];     // [bh][d][tok]  9,830,400
__device__ float g_kt[BH * HD * NT];     // 19,365,888
__device__ float g_vt[BH * HD * NT];     // 19,365,888
__device__ float g_qmT[NQ * NT];         // normalized q_mapper, transposed: [q][t]
__device__ float g_xmT[NT * NQ];         // normalized x_mapper, transposed: [t][q]
__device__ float g_y[NQ * BSZ * E];      // attention output in [Nq*BSZ, E] layout

// ---------------------------------------------------------------------------
// 128x128x16 SGEMM:  C[M,N] = A[M,K] @ W[N,K]^T + bias[N]
// SCATTER=true  -> C written as [( (b*NH+h)*HD + d ) * TOK + tok], m=(tok*BSZ+b)
// SCATTER=false -> C row-major [M,768]
// ---------------------------------------------------------------------------
template<bool SCATTER>
__global__ __launch_bounds__(256, 2)
void gemm_k(const float* __restrict__ A, const float* __restrict__ W,
            const float* __restrict__ bias, float* __restrict__ C,
            int K, int TOK)
{
    __shared__ float As[16][132];
    __shared__ float Bs[16][132];

    const int tid = threadIdx.x;
    const int m0 = blockIdx.y * 128;
    const int n0 = blockIdx.x * 128;

    const int lr = tid >> 2;           // 0..63
    const int lc = (tid & 3) << 2;     // 0,4,8,12

    const float* Ap = A + (size_t)(m0 + lr) * K + lc;
    const float* Wp = W + (size_t)(n0 + lr) * K + lc;

    float4 a0 = *(const float4*)Ap;
    float4 a1 = *(const float4*)(Ap + (size_t)64 * K);
    float4 b0 = *(const float4*)Wp;
    float4 b1 = *(const float4*)(Wp + (size_t)64 * K);

    float acc[8][8];
#pragma unroll
    for (int i = 0; i < 8; i++)
#pragma unroll
        for (int j = 0; j < 8; j++) acc[i][j] = 0.0f;

    const int tx = (tid & 15) << 3;    // n offset within tile
    const int ty = (tid >> 4) << 3;    // m offset within tile

    for (int kt = 0; kt < K; kt += 16) {
        As[lc + 0][lr]      = a0.x; As[lc + 1][lr]      = a0.y;
        As[lc + 2][lr]      = a0.z; As[lc + 3][lr]      = a0.w;
        As[lc + 0][lr + 64] = a1.x; As[lc + 1][lr + 64] = a1.y;
        As[lc + 2][lr + 64] = a1.z; As[lc + 3][lr + 64] = a1.w;
        Bs[lc + 0][lr]      = b0.x; Bs[lc + 1][lr]      = b0.y;
        Bs[lc + 2][lr]      = b0.z; Bs[lc + 3][lr]      = b0.w;
        Bs[lc + 0][lr + 64] = b1.x; Bs[lc + 1][lr + 64] = b1.y;
        Bs[lc + 2][lr + 64] = b1.z; Bs[lc + 3][lr + 64] = b1.w;
        __syncthreads();

        if (kt + 16 < K) {
            a0 = *(const float4*)(Ap + kt + 16);
            a1 = *(const float4*)(Ap + (size_t)64 * K + kt + 16);
            b0 = *(const float4*)(Wp + kt + 16);
            b1 = *(const float4*)(Wp + (size_t)64 * K + kt + 16);
        }

#pragma unroll
        for (int k = 0; k < 16; k++) {
            float ra[8], rb[8];
            *(float4*)&ra[0] = *(const float4*)&As[k][ty];
            *(float4*)&ra[4] = *(const float4*)&As[k][ty + 4];
            *(float4*)&rb[0] = *(const float4*)&Bs[k][tx];
            *(float4*)&rb[4] = *(const float4*)&Bs[k][tx + 4];
#pragma unroll
            for (int i = 0; i < 8; i++)
#pragma unroll
                for (int j = 0; j < 8; j++)
                    acc[i][j] = fmaf(ra[i], rb[j], acc[i][j]);
        }
        __syncthreads();
    }

    if (SCATTER) {
#pragma unroll
        for (int i = 0; i < 8; i++) {
            int m   = m0 + ty + i;
            int tok = m >> 7;          // / BSZ (=128)
            int b   = m & 127;
#pragma unroll
            for (int j = 0; j < 8; j++) {
                int col = n0 + tx + j;
                int h = col >> 6, d = col & 63;
                C[(size_t)(((b * NH + h) << 6) + d) * TOK + tok] = acc[i][j] + bias[col];
            }
        }
    } else {
#pragma unroll
        for (int i = 0; i < 8; i++) {
            int m = m0 + ty + i;
#pragma unroll
            for (int j = 0; j < 8; j++) {
                int col = n0 + tx + j;
                C[(size_t)m * 768 + col] = acc[i][j] + bias[col];
            }
        }
    }
}

// ---------------------------------------------------------------------------
// Row L2 normalize in-place:  x <- x / max(||x||, 1e-12).  One warp per row.
// ---------------------------------------------------------------------------
__global__ void norm_rows(float* __restrict__ X, int R, int L)
{
    int row  = blockIdx.x * (blockDim.x >> 5) + (threadIdx.x >> 5);
    if (row >= R) return;
    int lane = threadIdx.x & 31;
    float* x = X + (size_t)row * L;
    float ss = 0.0f;
    for (int i = lane; i < L; i += 32) { float v = x[i]; ss += v * v; }
#pragma unroll
    for (int o = 16; o; o >>= 1) ss += __shfl_xor_sync(0xffffffffu, ss, o);
    float s = 1.0f / fmaxf(sqrtf(ss), 1e-12f);
    for (int i = lane; i < L; i += 32) x[i] *= s;
}

// ---------------------------------------------------------------------------
// Normalize + transpose mapper matrices.
//   q_mapper [NT,NQ] (norm over NQ) -> qmT [NQ,NT]   (qmT[q*NT+t])
//   x_mapper [NQ,NT] (norm over NT) -> xmT [NT,NQ]   (xmT[t*NQ+q])
// One warp per source row.
// ---------------------------------------------------------------------------
__global__ void norm_map(const float* __restrict__ qm, const float* __restrict__ xm,
                         float* __restrict__ qmT, float* __restrict__ xmT)
{
    int row  = blockIdx.x * (blockDim.x >> 5) + (threadIdx.x >> 5);
    int lane = threadIdx.x & 31;
    if (row < NT) {
        const float* x = qm + row * NQ;
        float ss = 0.0f;
        for (int i = lane; i < NQ; i += 32) { float v = x[i]; ss += v * v; }
#pragma unroll
        for (int o = 16; o; o >>= 1) ss += __shfl_xor_sync(0xffffffffu, ss, o);
        float s = 1.0f / fmaxf(sqrtf(ss), 1e-12f);
        for (int i = lane; i < NQ; i += 32) qmT[i * NT + row] = x[i] * s;
    } else if (row < NT + NQ) {
        int r = row - NT;
        const float* x = xm + r * NT;
        float ss = 0.0f;
        for (int i = lane; i < NT; i += 32) { float v = x[i]; ss += v * v; }
#pragma unroll
        for (int o = 16; o; o >>= 1) ss += __shfl_xor_sync(0xffffffffu, ss, o);
        float s = 1.0f / fmaxf(sqrtf(ss), 1e-12f);
        for (int i = lane; i < NT; i += 32) xmT[i * NQ + r] = x[i] * s;
    }
}

// ---------------------------------------------------------------------------
// Fused per-(b,h) attention: qm -> attn(softmax) -> x -> out, all in SMEM.
// 512 threads, one CTA per (b*NH+h). Writes y[(q*BSZ+b)*E + h*64 + d].
// SMEM: sQ[64][101] | sK[64][197] (kn, later v) | sM[64][197] (qm, later x)
//       | sA[64][65] (attn)
// ---------------------------------------------------------------------------
#define SQP 101
#define SKP 197
#define SAP 65
#define ATTN_SMEM_FLOATS (64*SQP + 64*SKP + 64*SKP + 64*SAP)   // 35840

__global__ __launch_bounds__(512, 1)
void attn_kernel(const float* __restrict__ q_t, const float* __restrict__ k_t,
                 const float* __restrict__ v_t, const float* __restrict__ qmT,
                 const float* __restrict__ xmT, const float* __restrict__ temp,
                 float* __restrict__ y)
{
    extern __shared__ float sm[];
    float* sQ = sm;
    float* sK = sQ + 64 * SQP;
    float* sM = sK + 64 * SKP;
    float* sA = sM + 64 * SKP;

    const int bh = blockIdx.x;
    const int b  = bh / NH;
    const int h  = bh % NH;
    const float* qp = q_t + (size_t)bh * HD * NQ;
    const float* kp = k_t + (size_t)bh * HD * NT;
    const float* vp = v_t + (size_t)bh * HD * NT;

    const int tid  = threadIdx.x;
    const int w    = tid >> 5;
    const int lane = tid & 31;

    // Phase 0: load qn and kn tiles
    for (int i = tid; i < HD * NQ; i += 512) {
        int d = i / NQ, q = i % NQ;
        sQ[d * SQP + q] = qp[i];
    }
    for (int i = tid; i < HD * NT; i += 512) sK[i] = kp[i];
    __syncthreads();

    // Phase 1: qm[d,t] = sum_q sQ[d,q] * qmT[q,t]   (16 warps: 8 d-blocks x 2 t-halves)
    {
        const int d0 = (w >> 1) * 8;
        const int tb = lane + ((w & 1) << 5);
        for (int t = tb; t < NT; t += 64) {
            float acc[8] = {0,0,0,0,0,0,0,0};
            for (int q = 0; q < NQ; q++) {
                float m = qmT[q * NT + t];
#pragma unroll
                for (int i = 0; i < 8; i++)
                    acc[i] = fmaf(sQ[(d0 + i) * SQP + q], m, acc[i]);
            }
#pragma unroll
            for (int i = 0; i < 8; i++) sM[(d0 + i) * SKP + t] = acc[i];
        }
    }
    __syncthreads();

    // Phase 2: attn[d,e] = temp[h] * sum_t qm[d,t] * kn[e,t]   (2x4 microtile)
    {
        const float tval = temp[h];
        const int e0 = (tid & 15) << 2;   // 0..60
        const int d0 = (tid >> 4) << 1;   // 0..62
        float acc[2][4] = {{0,0,0,0},{0,0,0,0}};
        for (int t = 0; t < NT; t++) {
            float a0 = sM[d0 * SKP + t];
            float a1 = sM[(d0 + 1) * SKP + t];
            float bv[4];
#pragma unroll
            for (int j = 0; j < 4; j++) bv[j] = sK[(e0 + j) * SKP + t];
#pragma unroll
            for (int j = 0; j < 4; j++) {
                acc[0][j] = fmaf(a0, bv[j], acc[0][j]);
                acc[1][j] = fmaf(a1, bv[j], acc[1][j]);
            }
        }
#pragma unroll
        for (int i = 0; i < 2; i++)
#pragma unroll
            for (int j = 0; j < 4; j++)
                sA[(d0 + i) * SAP + e0 + j] = acc[i][j] * tval;
    }
    __syncthreads();

    // Phase 3: softmax rows of sA (threads 0..63) while others load v into sK
    if (tid < 64) {
        float* r = sA + tid * SAP;
        float mx = r[0];
#pragma unroll 8
        for (int e = 1; e < 64; e++) mx = fmaxf(mx, r[e]);
        float s = 0.0f;
        for (int e = 0; e < 64; e++) { float ev = expf(r[e] - mx); r[e] = ev; s += ev; }
        float inv = 1.0f / s;
        for (int e = 0; e < 64; e++) r[e] *= inv;
    } else {
        for (int i = tid - 64; i < HD * NT; i += 448) sK[i] = vp[i];
    }
    __syncthreads();

    // Phase 4: x[d,t] = sum_e attn[d,e] * v[e,t]  -> overwrite sM
    {
        const int d0 = (w >> 1) * 8;
        const int tb = lane + ((w & 1) << 5);
        for (int t = tb; t < NT; t += 64) {
            float acc[8] = {0,0,0,0,0,0,0,0};
            for (int e = 0; e < 64; e++) {
                float vv = sK[e * SKP + t];
#pragma unroll
                for (int i = 0; i < 8; i++)
                    acc[i] = fmaf(sA[(d0 + i) * SAP + e], vv, acc[i]);
            }
#pragma unroll
            for (int i = 0; i < 8; i++) sM[(d0 + i) * SKP + t] = acc[i];
        }
    }
    __syncthreads();

    // Phase 5: out[d,q] = sum_t x[d,t] * xmT[t,q]; write y[(q*BSZ+b)*E + h*64 + d]
    {
        const int q0 = w * 8;                 // warps 0..12 active
        if (q0 < NQ) {
            const int qlim = NQ - q0;         // >= 1
            const int d = lane;               // handles d and d+32
            float acc0[8] = {0,0,0,0,0,0,0,0};
            float acc1[8] = {0,0,0,0,0,0,0,0};
            for (int t = 0; t < NT; t++) {
                float x0 = sM[d * SKP + t];
                float x1 = sM[(d + 32) * SKP + t];
#pragma unroll
                for (int j = 0; j < 8; j++) {
                    float xv = (j < qlim) ? xmT[t * NQ + q0 + j] : 0.0f;
                    acc0[j] = fmaf(x0, xv, acc0[j]);
                    acc1[j] = fmaf(x1, xv, acc1[j]);
                }
            }
#pragma unroll
            for (int j = 0; j < 8; j++) {
                if (j < qlim) {
                    size_t base = ((size_t)(q0 + j) * BSZ + b) * E + h * HD;
                    y[base + d]      = acc0[j];
                    y[base + d + 32] = acc1[j];
                }
            }
        }
    }
}

// ---------------------------------------------------------------------------
// Launch
// ---------------------------------------------------------------------------
extern "C" void kernel_launch(void* const* d_in, const int* in_sizes, int n_in,
                              void* d_out, int out_size)
{
    const float* query = (const float*)d_in[0];
    const float* key   = (const float*)d_in[1];
    const float* value = (const float*)d_in[2];
    const float* ipw   = (const float*)d_in[3];   // [3E, E]
    const float* ipb   = (const float*)d_in[4];   // [3E]
    const float* opw   = (const float*)d_in[5];   // [E, E]
    const float* opb   = (const float*)d_in[6];   // [E]
    const float* temp  = (const float*)d_in[7];   // [NH]
    const float* qmap  = (const float*)d_in[8];   // [NT, NQ]
    const float* xmap  = (const float*)d_in[9];   // [NQ, NT]
    float* out = (float*)d_out;

    float *qt, *kt, *vt, *qmT, *xmT, *y;
    cudaGetSymbolAddress((void**)&qt,  g_qt);
    cudaGetSymbolAddress((void**)&kt,  g_kt);
    cudaGetSymbolAddress((void**)&vt,  g_vt);
    cudaGetSymbolAddress((void**)&qmT, g_qmT);
    cudaGetSymbolAddress((void**)&xmT, g_xmT);
    cudaGetSymbolAddress((void**)&y,   g_y);

    // 1) Projections into [bh][d][tok] layout
    dim3 gq(6, (NQ * BSZ) / 128);   // (6, 100)
    dim3 gk(6, (NT * BSZ) / 128);   // (6, 197)
    gemm_k<true><<<gq, 256>>>(query, ipw,             ipb,         qt, E, NQ);
    gemm_k<true><<<gk, 256>>>(key,   ipw + E * E,     ipb + E,     kt, E, NT);
    gemm_k<true><<<gk, 256>>>(value, ipw + 2 * E * E, ipb + 2 * E, vt, E, NT);

    // 2) L2 normalize channel rows of q and k (over tokens)
    norm_rows<<<(BH * HD) / 8, 256>>>(qt, BH * HD, NQ);
    norm_rows<<<(BH * HD) / 8, 256>>>(kt, BH * HD, NT);

    // 3) Normalize + transpose mapper matrices
    norm_map<<<(NT + NQ + 7) / 8, 256>>>(qmap, xmap, qmT, xmT);

    // 4) Fused attention per (b,h)
    cudaFuncSetAttribute(attn_kernel, cudaFuncAttributeMaxDynamicSharedMemorySize,
                         ATTN_SMEM_FLOATS * sizeof(float));
    attn_kernel<<<BH, 512, ATTN_SMEM_FLOATS * sizeof(float)>>>(qt, kt, vt, qmT, xmT, temp, y);

    // 5) Output projection -> d_out [NQ*BSZ, E]
    gemm_k<false><<<gq, 256>>>(y, opw, opb, out, E, 0);
}

// round 4
// speedup vs baseline: 1.6668x; 1.6668x over previous
#include <cuda_runtime.h>
#include <cuda_bf16.h>
#include <math.h>
#include <cstdint>

// Problem constants
#define NQ   100
#define NT   197
#define BSZ  128
#define E    768
#define NH   12
#define HD   64
#define BH   (BSZ*NH)          // 1536

// ---------------------------------------------------------------------------
// Device scratch (no cudaMalloc allowed). q/k/v stay row-major [M][E].
// ---------------------------------------------------------------------------
__device__ float g_qt[NQ * BSZ * E];
__device__ float g_kt[NT * BSZ * E];
__device__ float g_vt[NT * BSZ * E];
__device__ float g_qmT[NQ * NT];
__device__ float g_xmT[NT * NQ];
__device__ float g_y[NQ * BSZ * E];

// ---------------------------------------------------------------------------
// mma.sync tf32 GEMM:  C[M,N=768] = A[M,K=768] @ W[N,K]^T + bias[N]
// CTA tile 128x128, 8 warps (2M x 4N), warp tile 64x32, m16n8k8 tf32 MMA.
// 3-stage cp.async pipeline, K-chunks of 32 floats.
// ---------------------------------------------------------------------------
#define PAD       36                       // padded row stride (floats)
#define MAT_F     (128 * PAD)              // floats per matrix tile (A or B)
#define STG_F     (2 * MAT_F)              // floats per stage
#define GEMM_SMEM (3 * STG_F * 4)          // 110592 bytes

__device__ __forceinline__ void cpa16(uint32_t dst, const void* src) {
    asm volatile("cp.async.cg.shared.global [%0], [%1], 16;" :: "r"(dst), "l"(src));
}
__device__ __forceinline__ uint32_t smem_u32(const void* p) {
    uint32_t a;
    asm("{ .reg .u64 t; cvta.to.shared.u64 t, %1; cvt.u32.u64 %0, t; }"
        : "=r"(a) : "l"(p));
    return a;
}
__device__ __forceinline__ uint32_t f2tf32(float f) {
    uint32_t r;
    asm("cvt.rna.tf32.f32 %0, %1;" : "=r"(r) : "f"(f));
    return r;
}
__device__ __forceinline__ void mma_tf32(float* c, const uint32_t* a, const uint32_t* b) {
    asm volatile(
        "mma.sync.aligned.m16n8k8.row.col.f32.tf32.tf32.f32 "
        "{%0,%1,%2,%3}, {%4,%5,%6,%7}, {%8,%9}, {%0,%1,%2,%3};"
        : "+f"(c[0]), "+f"(c[1]), "+f"(c[2]), "+f"(c[3])
        : "r"(a[0]), "r"(a[1]), "r"(a[2]), "r"(a[3]), "r"(b[0]), "r"(b[1]));
}

__global__ __launch_bounds__(256, 2)
void gemm_mma(const float* __restrict__ A, const float* __restrict__ W,
              const float* __restrict__ bias, float* __restrict__ C)
{
    extern __shared__ float sm[];
    const int tid  = threadIdx.x;
    const int lane = tid & 31;
    const int wid  = tid >> 5;
    const int m0 = blockIdx.y * 128, n0 = blockIdx.x * 128;
    const int wm = (wid >> 2) * 64;          // warp M offset (0 / 64)
    const int wn = (wid & 3) * 32;           // warp N offset (0..96)

    // producer mapping: each thread loads 64B of one row of A and of B per stage
    const int prow = tid >> 1;               // 0..127
    const int phal = (tid & 1) * 16;         // float offset within row (0 / 16)
    const float* gA = A + (size_t)(m0 + prow) * E + phal;
    const float* gB = W + (size_t)(n0 + prow) * E + phal;
    const uint32_t sbase = smem_u32(sm);
    const uint32_t sArow = sbase + (prow * PAD + phal) * 4;
    const uint32_t sBrow = sArow + MAT_F * 4;

#define LOAD_STAGE(st, kc) do { \
    const uint32_t so = (uint32_t)(st) * (STG_F * 4); \
    const float* ga = gA + (kc) * 32; \
    const float* gb = gB + (kc) * 32; \
    cpa16(sArow + so,      ga);      cpa16(sArow + so + 16, ga + 4); \
    cpa16(sArow + so + 32, ga + 8);  cpa16(sArow + so + 48, ga + 12); \
    cpa16(sBrow + so,      gb);      cpa16(sBrow + so + 16, gb + 4); \
    cpa16(sBrow + so + 32, gb + 8);  cpa16(sBrow + so + 48, gb + 12); \
    asm volatile("cp.async.commit_group;"); \
} while (0)

    LOAD_STAGE(0, 0);
    LOAD_STAGE(1, 1);
    LOAD_STAGE(2, 2);

    float acc[4][4][4];
#pragma unroll
    for (int i = 0; i < 4; i++)
#pragma unroll
        for (int j = 0; j < 4; j++)
#pragma unroll
            for (int k = 0; k < 4; k++) acc[i][j][k] = 0.0f;

    const int r = lane >> 2;     // 0..7
    const int q = lane & 3;      // 0..3

    for (int kc = 0; kc < 24; kc++) {
        asm volatile("cp.async.wait_group 2;");
        __syncthreads();
        const float* sA = sm + (kc % 3) * STG_F;
        const float* sB = sA + MAT_F;

#pragma unroll
        for (int s = 0; s < 4; s++) {
            const int k0 = s * 8 + q;
            uint32_t bf[4][2];
#pragma unroll
            for (int nt = 0; nt < 4; nt++) {
                const float* bp = sB + (wn + nt * 8 + r) * PAD + k0;
                bf[nt][0] = f2tf32(bp[0]);
                bf[nt][1] = f2tf32(bp[4]);
            }
#pragma unroll
            for (int mt = 0; mt < 4; mt++) {
                const float* ap = sA + (wm + mt * 16 + r) * PAD + k0;
                uint32_t af[4];
                af[0] = f2tf32(ap[0]);
                af[1] = f2tf32(ap[8 * PAD]);
                af[2] = f2tf32(ap[4]);
                af[3] = f2tf32(ap[8 * PAD + 4]);
#pragma unroll
                for (int nt = 0; nt < 4; nt++)
                    mma_tf32(acc[mt][nt], af, bf[nt]);
            }
        }
        __syncthreads();
        if (kc + 3 < 24) {
            LOAD_STAGE(kc % 3, kc + 3);
        } else {
            asm volatile("cp.async.commit_group;");
        }
    }

    // epilogue: bias add + row-major store (float2 per c-pair)
#pragma unroll
    for (int mt = 0; mt < 4; mt++) {
        const int row = m0 + wm + mt * 16 + r;
#pragma unroll
        for (int nt = 0; nt < 4; nt++) {
            const int col = n0 + wn + nt * 8 + 2 * q;
            const float b0 = bias[col], b1 = bias[col + 1];
            *(float2*)&C[(size_t)row * E + col] =
                make_float2(acc[mt][nt][0] + b0, acc[mt][nt][1] + b1);
            *(float2*)&C[(size_t)(row + 8) * E + col] =
                make_float2(acc[mt][nt][2] + b0, acc[mt][nt][3] + b1);
        }
    }
#undef LOAD_STAGE
}

// ---------------------------------------------------------------------------
// Normalize + transpose mapper matrices.
// ---------------------------------------------------------------------------
__global__ void norm_map(const float* __restrict__ qm, const float* __restrict__ xm,
                         float* __restrict__ qmT, float* __restrict__ xmT)
{
    int row  = blockIdx.x * (blockDim.x >> 5) + (threadIdx.x >> 5);
    int lane = threadIdx.x & 31;
    if (row < NT) {
        const float* x = qm + row * NQ;
        float ss = 0.0f;
        for (int i = lane; i < NQ; i += 32) { float v = x[i]; ss += v * v; }
#pragma unroll
        for (int o = 16; o; o >>= 1) ss += __shfl_xor_sync(0xffffffffu, ss, o);
        float s = 1.0f / fmaxf(sqrtf(ss), 1e-12f);
        for (int i = lane; i < NQ; i += 32) qmT[i * NT + row] = x[i] * s;
    } else if (row < NT + NQ) {
        int r = row - NT;
        const float* x = xm + r * NT;
        float ss = 0.0f;
        for (int i = lane; i < NT; i += 32) { float v = x[i]; ss += v * v; }
#pragma unroll
        for (int o = 16; o; o >>= 1) ss += __shfl_xor_sync(0xffffffffu, ss, o);
        float s = 1.0f / fmaxf(sqrtf(ss), 1e-12f);
        for (int i = lane; i < NT; i += 32) xmT[i * NQ + r] = x[i] * s;
    }
}

// ---------------------------------------------------------------------------
// Fused per-(b,h) attention with in-SMEM q/k L2 normalization.
// q/k/v are row-major [tok*BSZ+b][E]; gather 64-float rows per token.
// ---------------------------------------------------------------------------
#define SQP 101
#define SKP 197
#define SAP 65
#define ATTN_SMEM_FLOATS (64*SQP + 64*SKP + 64*SKP + 64*SAP)   // 35840
#define ROWSTR ((size_t)BSZ * E)                               // 98304

__global__ __launch_bounds__(512, 1)
void attn_kernel(const float* __restrict__ q_t, const float* __restrict__ k_t,
                 const float* __restrict__ v_t, const float* __restrict__ qmT,
                 const float* __restrict__ xmT, const float* __restrict__ temp,
                 float* __restrict__ y)
{
    extern __shared__ float sm[];
    float* sQ = sm;
    float* sK = sQ + 64 * SQP;
    float* sM = sK + 64 * SKP;
    float* sA = sM + 64 * SKP;

    const int bh = blockIdx.x;
    const int b  = bh / NH;
    const int h  = bh % NH;
    const float* qp = q_t + (size_t)b * E + h * HD;
    const float* kp = k_t + (size_t)b * E + h * HD;
    const float* vp = v_t + (size_t)b * E + h * HD;

    const int tid  = threadIdx.x;
    const int w    = tid >> 5;
    const int lane = tid & 31;

    // Phase 0: gather q and k tiles (64 contiguous floats per token)
    for (int i = tid; i < NQ * 64; i += 512) {
        int tok = i >> 6, d = i & 63;
        sQ[d * SQP + tok] = qp[(size_t)tok * ROWSTR + d];
    }
    for (int i = tid; i < NT * 64; i += 512) {
        int tok = i >> 6, d = i & 63;
        sK[d * SKP + tok] = kp[(size_t)tok * ROWSTR + d];
    }
    __syncthreads();

    // Phase 0.5: fused L2 normalization over tokens
    for (int rr = w; rr < 128; rr += 16) {
        float* x; int L;
        if (rr < 64) { x = sQ + rr * SQP; L = NQ; }
        else         { x = sK + (rr - 64) * SKP; L = NT; }
        float ss = 0.0f;
        for (int i = lane; i < L; i += 32) { float v = x[i]; ss += v * v; }
#pragma unroll
        for (int o = 16; o; o >>= 1) ss += __shfl_xor_sync(0xffffffffu, ss, o);
        float sc = 1.0f / fmaxf(sqrtf(ss), 1e-12f);
        for (int i = lane; i < L; i += 32) x[i] *= sc;
    }
    __syncthreads();

    // Phase 1: qm[d,t] = sum_q sQ[d,q] * qmT[q,t]
    {
        const int d0 = (w >> 1) * 8;
        const int tb = lane + ((w & 1) << 5);
        for (int t = tb; t < NT; t += 64) {
            float acc[8] = {0,0,0,0,0,0,0,0};
            for (int qq = 0; qq < NQ; qq++) {
                float m = qmT[qq * NT + t];
#pragma unroll
                for (int i = 0; i < 8; i++)
                    acc[i] = fmaf(sQ[(d0 + i) * SQP + qq], m, acc[i]);
            }
#pragma unroll
            for (int i = 0; i < 8; i++) sM[(d0 + i) * SKP + t] = acc[i];
        }
    }
    __syncthreads();

    // Phase 2: attn[d,e] = temp[h] * sum_t qm[d,t] * kn[e,t]
    {
        const float tval = temp[h];
        const int e0 = (tid & 15) << 2;
        const int d0 = (tid >> 4) << 1;
        float acc[2][4] = {{0,0,0,0},{0,0,0,0}};
        for (int t = 0; t < NT; t++) {
            float a0 = sM[d0 * SKP + t];
            float a1 = sM[(d0 + 1) * SKP + t];
            float bv[4];
#pragma unroll
            for (int j = 0; j < 4; j++) bv[j] = sK[(e0 + j) * SKP + t];
#pragma unroll
            for (int j = 0; j < 4; j++) {
                acc[0][j] = fmaf(a0, bv[j], acc[0][j]);
                acc[1][j] = fmaf(a1, bv[j], acc[1][j]);
            }
        }
#pragma unroll
        for (int i = 0; i < 2; i++)
#pragma unroll
            for (int j = 0; j < 4; j++)
                sA[(d0 + i) * SAP + e0 + j] = acc[i][j] * tval;
    }
    __syncthreads();

    // Phase 3: softmax rows of sA (threads 0..63) while others gather v into sK
    if (tid < 64) {
        float* rr = sA + tid * SAP;
        float mx = rr[0];
#pragma unroll 8
        for (int e = 1; e < 64; e++) mx = fmaxf(mx, rr[e]);
        float s = 0.0f;
        for (int e = 0; e < 64; e++) { float ev = expf(rr[e] - mx); rr[e] = ev; s += ev; }
        float inv = 1.0f / s;
        for (int e = 0; e < 64; e++) rr[e] *= inv;
    } else {
        for (int i = tid - 64; i < NT * 64; i += 448) {
            int tok = i >> 6, d = i & 63;
            sK[d * SKP + tok] = vp[(size_t)tok * ROWSTR + d];
        }
    }
    __syncthreads();

    // Phase 4: x[d,t] = sum_e attn[d,e] * v[e,t]  -> overwrite sM
    {
        const int d0 = (w >> 1) * 8;
        const int tb = lane + ((w & 1) << 5);
        for (int t = tb; t < NT; t += 64) {
            float acc[8] = {0,0,0,0,0,0,0,0};
            for (int e = 0; e < 64; e++) {
                float vv = sK[e * SKP + t];
#pragma unroll
                for (int i = 0; i < 8; i++)
                    acc[i] = fmaf(sA[(d0 + i) * SAP + e], vv, acc[i]);
            }
#pragma unroll
            for (int i = 0; i < 8; i++) sM[(d0 + i) * SKP + t] = acc[i];
        }
    }
    __syncthreads();

    // Phase 5: out[d,q] = sum_t x[d,t] * xmT[t,q]; write y[(q*BSZ+b)*E + h*64 + d]
    {
        const int q0 = w * 8;
        if (q0 < NQ) {
            const int qlim = NQ - q0;
            const int d = lane;
            float acc0[8] = {0,0,0,0,0,0,0,0};
            float acc1[8] = {0,0,0,0,0,0,0,0};
            for (int t = 0; t < NT; t++) {
                float x0 = sM[d * SKP + t];
                float x1 = sM[(d + 32) * SKP + t];
#pragma unroll
                for (int j = 0; j < 8; j++) {
                    float xv = (j < qlim) ? xmT[t * NQ + q0 + j] : 0.0f;
                    acc0[j] = fmaf(x0, xv, acc0[j]);
                    acc1[j] = fmaf(x1, xv, acc1[j]);
                }
            }
#pragma unroll
            for (int j = 0; j < 8; j++) {
                if (j < qlim) {
                    size_t base = ((size_t)(q0 + j) * BSZ + b) * E + h * HD;
                    y[base + d]      = acc0[j];
                    y[base + d + 32] = acc1[j];
                }
            }
        }
    }
}

// ---------------------------------------------------------------------------
// Launch
// ---------------------------------------------------------------------------
extern "C" void kernel_launch(void* const* d_in, const int* in_sizes, int n_in,
                              void* d_out, int out_size)
{
    const float* query = (const float*)d_in[0];
    const float* key   = (const float*)d_in[1];
    const float* value = (const float*)d_in[2];
    const float* ipw   = (const float*)d_in[3];
    const float* ipb   = (const float*)d_in[4];
    const float* opw   = (const float*)d_in[5];
    const float* opb   = (const float*)d_in[6];
    const float* temp  = (const float*)d_in[7];
    const float* qmap  = (const float*)d_in[8];
    const float* xmap  = (const float*)d_in[9];
    float* out = (float*)d_out;

    float *qt, *kt, *vt, *qmT, *xmT, *y;
    cudaGetSymbolAddress((void**)&qt,  g_qt);
    cudaGetSymbolAddress((void**)&kt,  g_kt);
    cudaGetSymbolAddress((void**)&vt,  g_vt);
    cudaGetSymbolAddress((void**)&qmT, g_qmT);
    cudaGetSymbolAddress((void**)&xmT, g_xmT);
    cudaGetSymbolAddress((void**)&y,   g_y);

    cudaFuncSetAttribute(gemm_mma, cudaFuncAttributeMaxDynamicSharedMemorySize, GEMM_SMEM);
    cudaFuncSetAttribute(attn_kernel, cudaFuncAttributeMaxDynamicSharedMemorySize,
                         ATTN_SMEM_FLOATS * sizeof(float));

    // 1) Projections (mma.sync tf32), row-major outputs
    dim3 gq(6, (NQ * BSZ) / 128);   // (6, 100)
    dim3 gk(6, (NT * BSZ) / 128);   // (6, 197)
    gemm_mma<<<gq, 256, GEMM_SMEM>>>(query, ipw,             ipb,         qt);
    gemm_mma<<<gk, 256, GEMM_SMEM>>>(key,   ipw + E * E,     ipb + E,     kt);
    gemm_mma<<<gk, 256, GEMM_SMEM>>>(value, ipw + 2 * E * E, ipb + 2 * E, vt);

    // 2) Normalize + transpose mapper matrices
    norm_map<<<(NT + NQ + 7) / 8, 256>>>(qmap, xmap, qmT, xmT);

    // 3) Fused attention per (b,h) (includes q/k L2 norm)
    attn_kernel<<<BH, 512, ATTN_SMEM_FLOATS * sizeof(float)>>>(qt, kt, vt, qmT, xmT, temp, y);

    // 4) Output projection -> d_out
    gemm_mma<<<gq, 256, GEMM_SMEM>>>(y, opw, opb, out);
}